// round 6
// baseline (speedup 1.0000x reference)
#include <cuda_runtime.h>
#include <stdint.h>

// Unpack padded [B, Lmax, H, D] fp32 -> packed [N, H, D], N = sum(lengths).
// Row size H*D = 16*128 = 2048 floats = 8192 bytes.
// N derived host-side from out_size (= N * 2048).
//
// lengths dtype is ambiguous (JAX x64-disabled downcasts jnp.int64 -> int32).
// We detect on-device: parse as contiguous int32 AND as int64-low-words; the
// parse whose sum equals N is the real one. Values are < Lmax=4096 so the
// low 32-bit word of a little-endian int64 carries the full value.

#define ROW_ELEMS 2048
#define ROW_VEC4  (ROW_ELEMS / 4)   // 512
#define MAX_B     32

__global__ void __launch_bounds__(256) unpack_rows_kernel(
    const float* __restrict__ in,       // [B, Lmax, H, D]
    const int* __restrict__ lengths_raw,// [B] int32 words (dtype detected below)
    float* __restrict__ out,            // [N, H, D]
    int B, int Lmax, int N)
{
    int n = blockIdx.x;
    if (n >= N) return;

    // --- dtype detection + prefix resolution (B is tiny; L1-resident) ---
    int len32[MAX_B];
    long long sum32 = 0, sum64 = 0;
    #pragma unroll 8
    for (int i = 0; i < B; ++i) {
        int a = __ldg(&lengths_raw[i]);         // contiguous int32 parse
        int c = __ldg(&lengths_raw[2 * i]);     // int64 low-word parse
        len32[i] = a;
        sum32 += a;
        sum64 += c;
    }
    bool is64 = (sum64 == (long long)N) && (sum32 != (long long)N);

    // Find batch b such that start[b] <= n < start[b] + len[b].
    int s = 0, b = 0, t = 0;
    #pragma unroll 8
    for (int i = 0; i < B; ++i) {
        int len = is64 ? __ldg(&lengths_raw[2 * i]) : len32[i];
        if (n >= s && n < s + len) { b = i; t = n - s; }
        s += len;
    }

    const float4* __restrict__ src =
        (const float4*)(in + ((size_t)b * Lmax + (size_t)t) * ROW_ELEMS);
    float4* __restrict__ dst = (float4*)(out + (size_t)n * ROW_ELEMS);

    // 512 float4 per row, 256 threads -> 2 independent LDG.128/STG.128 per thread.
    #pragma unroll
    for (int i = threadIdx.x; i < ROW_VEC4; i += 256) {
        dst[i] = src[i];
    }
}

extern "C" void kernel_launch(void* const* d_in, const int* in_sizes, int n_in,
                              void* d_out, int out_size)
{
    const float* packed = (const float*)d_in[0];   // [B, Lmax, H, D] fp32
    const int* lengths_raw = (const int*)d_in[1];  // [B] (int32 or int64 words)

    int B = in_sizes[1];                 // element count of lengths (8)
    if (B > MAX_B) B = MAX_B;
    long long total_in = in_sizes[0];    // B * Lmax * H * D
    int Lmax = (int)(total_in / ((long long)B * ROW_ELEMS)); // 4096

    int N = out_size / ROW_ELEMS;        // number of packed rows

    float* out = (float*)d_out;

    int grid = (N > 0) ? N : 1;          // always capture >=1 node
    unpack_rows_kernel<<<grid, 256>>>(packed, lengths_raw, out, B, Lmax, N);
}

// round 7
// speedup vs baseline: 1.0530x; 1.0530x over previous
#include <cuda_runtime.h>
#include <stdint.h>

// Unpack padded [B, Lmax, H, D] fp32 -> packed [N, H, D], N = sum(lengths).
// Row = H*D = 2048 floats = 512 float4 = 8 KB.
//
// v2: 4 rows per block, two-phase copy. Each thread front-batches 8
// independent LDG.128 (MLP_p1=8), then issues 8 STG.128. Streaming cache
// hints (.cs) since every byte is touched exactly once.
//
// lengths dtype detected on-device (JAX x64-off downcasts int64 -> int32):
// parse as contiguous int32 AND int64-low-words; whichever sums to N wins.

#define ROW_VEC4        512          // float4 per row
#define THREADS         256
#define VEC_PER_THREAD  (ROW_VEC4 / THREADS)   // 2
#define ROWS_PER_BLOCK  4
#define MAX_B           32

__global__ void __launch_bounds__(THREADS) unpack_rows4_kernel(
    const float4* __restrict__ in,        // [B, Lmax, 512] as float4
    const int* __restrict__ lengths_raw,  // [B] raw words
    float4* __restrict__ out,             // [N, 512] as float4
    int B, int Lmax, int N)
{
    const int n0 = blockIdx.x * ROWS_PER_BLOCK;

    // --- dtype detection (B tiny; L1-resident, uniform across threads) ---
    long long sum32 = 0, sum64 = 0;
    #pragma unroll 8
    for (int i = 0; i < B; ++i) {
        sum32 += __ldg(&lengths_raw[i]);
        sum64 += __ldg(&lengths_raw[2 * i]);
    }
    const bool is64 = (sum64 == (long long)N) && (sum32 != (long long)N);

    // --- resolve (b, t) for each of the 4 rows this block owns ---
    const float4* src[ROWS_PER_BLOCK];
    bool valid[ROWS_PER_BLOCK];
    #pragma unroll
    for (int r = 0; r < ROWS_PER_BLOCK; ++r) {
        const int n = n0 + r;
        valid[r] = (n < N);
        int s = 0, b = 0, t = 0;
        #pragma unroll 8
        for (int i = 0; i < B; ++i) {
            const int len = is64 ? __ldg(&lengths_raw[2 * i]) : __ldg(&lengths_raw[i]);
            if (n >= s && n < s + len) { b = i; t = n - s; }
            s += len;
        }
        src[r] = in + ((size_t)b * Lmax + (size_t)t) * ROW_VEC4;
    }

    // --- phase 1: 8 independent streaming loads (front-batched) ---
    float4 v[ROWS_PER_BLOCK * VEC_PER_THREAD];
    #pragma unroll
    for (int r = 0; r < ROWS_PER_BLOCK; ++r) {
        #pragma unroll
        for (int j = 0; j < VEC_PER_THREAD; ++j) {
            if (valid[r])
                v[r * VEC_PER_THREAD + j] =
                    __ldcs(&src[r][threadIdx.x + j * THREADS]);
        }
    }

    // --- phase 2: 8 streaming stores ---
    #pragma unroll
    for (int r = 0; r < ROWS_PER_BLOCK; ++r) {
        float4* dst = out + (size_t)(n0 + r) * ROW_VEC4;
        #pragma unroll
        for (int j = 0; j < VEC_PER_THREAD; ++j) {
            if (valid[r])
                __stcs(&dst[threadIdx.x + j * THREADS],
                       v[r * VEC_PER_THREAD + j]);
        }
    }
}

extern "C" void kernel_launch(void* const* d_in, const int* in_sizes, int n_in,
                              void* d_out, int out_size)
{
    const float4* packed = (const float4*)d_in[0];   // [B, Lmax, H, D] fp32
    const int* lengths_raw = (const int*)d_in[1];    // [B] (int32 or int64 words)

    int B = in_sizes[1];
    if (B > MAX_B) B = MAX_B;
    long long total_in = in_sizes[0];                     // B*Lmax*2048 floats
    int Lmax = (int)(total_in / ((long long)B * 2048));   // 4096

    int N = out_size / 2048;                              // packed rows

    float4* out = (float4*)d_out;

    int grid = (N + ROWS_PER_BLOCK - 1) / ROWS_PER_BLOCK;
    if (grid < 1) grid = 1;
    unpack_rows4_kernel<<<grid, THREADS>>>(packed, lengths_raw, out, B, Lmax, N);
}